// round 7
// baseline (speedup 1.0000x reference)
#include <cuda_runtime.h>
#include <cstdint>

// Kendall's tau loss via discordant-pair count (no ties in random normals):
//   loss = 4*D / (n(n-1)),  D = #{i<j : sign(p_i-p_j) != sign(t_i-t_j)}
// R7: scalar 4-instr pair kernel (2xFADD + LOP3 + LEA.HI). The packed-f32x2
// asm path (R3-R6) forced 64-bit register-pair constraints -> ~50% of issued
// slots were MOVs. Scalar ops give ptxas full freedom, natively balance
// fma/alu pipes (2:2), and cut issued instructions by ~20-50%.

#define TILE 256
#define NTH 128

__device__ unsigned long long g_cnt = 0;
__device__ unsigned int g_done = 0;

// c += (sign(pi + npj) != sign(ti + ntj))   [npj = -p_j etc.]
__device__ __forceinline__ void acc_pair(unsigned int& c,
                                         float pi, float ti,
                                         float npj, float ntj) {
    float dp = pi + npj;                 // FADD (fma pipe)
    float dt = ti + ntj;                 // FADD (fma pipe)
    unsigned int x = __float_as_uint(dp) ^ __float_as_uint(dt);  // LOP3 (alu)
    c += x >> 31;                        // LEA.HI (alu)
}

__global__ __launch_bounds__(NTH) void kt_kernel(
    const float* __restrict__ p, const float* __restrict__ t,
    float* __restrict__ out, int n)
{
    const int ntiles = (n + TILE - 1) / TILE;

    // Linear block id -> upper-triangular (bi, bj), bj >= bi.
    int b = blockIdx.x;
    int bi = 0;
    while (b >= ntiles - bi) { b -= ntiles - bi; ++bi; }
    const int bj = bi + b;

    __shared__ __align__(16) float snp[TILE];  // -p_j
    __shared__ __align__(16) float snt[TILE];  // -t_j

    const int tid = threadIdx.x;
    const int jb = bj * TILE;
    const int jlim = min(TILE, n - jb);

    #pragma unroll
    for (int k = tid; k < TILE; k += NTH) {
        if (k < jlim) {
            snp[k] = -p[jb + k];
            snt[k] = -t[jb + k];
        }
    }
    __syncthreads();

    const int ib = bi * TILE;
    unsigned int c0 = 0, c1 = 0, c2 = 0, c3 = 0;

    const bool full = (jlim == TILE) && (ib + TILE <= n);

    if (full && bi != bj) {
        // Full off-diagonal tile: all (i, j) valid. 2 rows/thread.
        const float p0 = p[ib + tid      ], t0 = t[ib + tid      ];
        const float p1 = p[ib + tid + NTH], t1 = t[ib + tid + NTH];

        const float4* SP4 = reinterpret_cast<const float4*>(snp);
        const float4* ST4 = reinterpret_cast<const float4*>(snt);

        #pragma unroll 8
        for (int k4 = 0; k4 < TILE / 4; ++k4) {
            const float4 jp = SP4[k4];   // LDS.128 broadcast: 4 j's of -p
            const float4 jt = ST4[k4];   // LDS.128 broadcast: 4 j's of -t
            acc_pair(c0, p0, t0, jp.x, jt.x);
            acc_pair(c1, p1, t1, jp.x, jt.x);
            acc_pair(c2, p0, t0, jp.y, jt.y);
            acc_pair(c3, p1, t1, jp.y, jt.y);
            acc_pair(c0, p0, t0, jp.z, jt.z);
            acc_pair(c1, p1, t1, jp.z, jt.z);
            acc_pair(c2, p0, t0, jp.w, jt.w);
            acc_pair(c3, p1, t1, jp.w, jt.w);
        }
    } else if (full) {
        // Diagonal tile: local j > local i.
        const float p0 = p[ib + tid      ], t0 = t[ib + tid      ];
        const float p1 = p[ib + tid + NTH], t1 = t[ib + tid + NTH];
        #pragma unroll 4
        for (int k = tid + 1; k < TILE; ++k)
            acc_pair(c0, p0, t0, snp[k], snt[k]);
        #pragma unroll 4
        for (int k = tid + NTH + 1; k < TILE; ++k)
            acc_pair(c1, p1, t1, snp[k], snt[k]);
    } else {
        // Partial tile (not hit for n=8192; kept for generality).
        #pragma unroll
        for (int r = 0; r < 2; ++r) {
            const int i = ib + tid + r * NTH;
            if (i < n) {
                const float pi = p[i], ti = t[i];
                for (int k = 0; k < jlim; ++k)
                    if (jb + k > i) acc_pair(c0, pi, ti, snp[k], snt[k]);
            }
        }
    }

    // Warp reduction: single REDUX.SUM.
    unsigned int cnt = __reduce_add_sync(0xFFFFFFFFu, (c0 + c1) + (c2 + c3));

    __shared__ unsigned int wsum[NTH / 32];
    if ((tid & 31) == 0) wsum[tid >> 5] = cnt;
    __syncthreads();

    if (tid == 0) {
        unsigned int total = 0;
        #pragma unroll
        for (int w = 0; w < NTH / 32; ++w) total += wsum[w];

        atomicAdd(&g_cnt, (unsigned long long)total);
        __threadfence();
        const unsigned int d = atomicAdd(&g_done, 1u);
        if (d == gridDim.x - 1) {
            const unsigned long long D = atomicAdd(&g_cnt, 0ULL);
            const double nn = (double)n;
            out[0] = (float)(4.0 * (double)D / (nn * (nn - 1.0)));
            g_cnt = 0ULL;   // reset for next graph replay
            g_done = 0u;
        }
    }
}

extern "C" void kernel_launch(void* const* d_in, const int* in_sizes, int n_in,
                              void* d_out, int out_size)
{
    const float* predictions = (const float*)d_in[0];
    const float* true_labels = (const float*)d_in[1];
    float* out = (float*)d_out;
    const int n = in_sizes[0];

    const int ntiles = (n + TILE - 1) / TILE;
    const int nblocks = ntiles * (ntiles + 1) / 2;

    kt_kernel<<<nblocks, NTH>>>(predictions, true_labels, out, n);
}

// round 8
// speedup vs baseline: 1.1400x; 1.1400x over previous
#include <cuda_runtime.h>
#include <cstdint>

// Kendall's tau loss via discordant-pair count (no ties in random normals):
//   loss = 4*D / (n(n-1)),  D = #{i<j : sign(p_i-p_j) != sign(t_i-t_j)}
// R8: single fused asm per pair (FADD2 -> xor of halves, MOV-free), dual-pipe
// accumulate (LEA.HI on alu / IMAD.HI on fma), single packed-u64 atomic
// epilogue (no threadfence), R3's proven 528x128 shape.

#define TILE 256
#define NTH 128

__device__ unsigned long long g_cnt = 0;  // bits[0:40) count, bits[40:) block ctr

__device__ __forceinline__ unsigned long long pack2(float lo, float hi) {
    unsigned long long r;
    asm("mov.b64 %0, {%1, %2};" : "=l"(r) : "f"(lo), "f"(hi));
    return r;
}

// xor of the two fp32 halves of (a + nb) [packed f32x2 add], single asm block
// so ptxas can alias lo/hi onto the FADD2 destination pair (no MOVs).
__device__ __forceinline__ unsigned int xor_word(unsigned long long a,
                                                 unsigned long long nb) {
    unsigned int r;
    asm("{\n\t"
        ".reg .b64 s;\n\t"
        ".reg .b32 lo, hi;\n\t"
        "add.rn.f32x2 s, %1, %2;\n\t"
        "mov.b64 {lo, hi}, s;\n\t"
        "xor.b32 %0, lo, hi;\n\t"
        "}" : "=r"(r) : "l"(a), "l"(nb));
    return r;
}

// alu-pipe accumulate: LEA.HI (c += bit31)
__device__ __forceinline__ void acc_alu(unsigned int& c, unsigned long long a,
                                        unsigned long long nb) {
    c += xor_word(a, nb) >> 31;
}
// fma-pipe accumulate: IMAD.HI.U32, multiplier ==2 but runtime-opaque
__device__ __forceinline__ void acc_fma(unsigned int& c, unsigned long long a,
                                        unsigned long long nb,
                                        unsigned int two) {
    unsigned int x = xor_word(a, nb);
    asm("mad.hi.u32 %0, %1, %2, %0;" : "+r"(c) : "r"(x), "r"(two));
}

__global__ __launch_bounds__(NTH) void kt_kernel(
    const float* __restrict__ p, const float* __restrict__ t,
    float* __restrict__ out, int n)
{
    const int ntiles = (n + TILE - 1) / TILE;
    const unsigned int two = (unsigned int)blockDim.x >> 6;  // ==2, opaque

    // Linear block id -> upper-triangular (bi, bj), bj >= bi.
    int b = blockIdx.x;
    int bi = 0;
    while (b >= ntiles - bi) { b -= ntiles - bi; ++bi; }
    const int bj = bi + b;

    __shared__ __align__(16) float2 snb[TILE];  // (-p_j, -t_j)

    const int tid = threadIdx.x;
    const int jb = bj * TILE;
    const int jlim = min(TILE, n - jb);

    #pragma unroll
    for (int k = tid; k < TILE; k += NTH)
        if (k < jlim) snb[k] = make_float2(-p[jb + k], -t[jb + k]);
    __syncthreads();

    const int ib = bi * TILE;
    unsigned int c0 = 0, c1 = 0;

    const bool full = (jlim == TILE) && (ib + TILE <= n);

    if (full && bi != bj) {
        // Full off-diagonal tile: all (i, j) valid. 2 rows/thread.
        const unsigned long long a0 = pack2(p[ib + tid      ], t[ib + tid      ]);
        const unsigned long long a1 = pack2(p[ib + tid + NTH], t[ib + tid + NTH]);

        const ulonglong2* B2 = reinterpret_cast<const ulonglong2*>(snb);
        #pragma unroll 8
        for (int k2 = 0; k2 < TILE / 2; ++k2) {
            const ulonglong2 bb = B2[k2];   // LDS.128: two j's
            acc_alu(c0, a0, bb.x);
            acc_fma(c1, a1, bb.x, two);
            acc_alu(c0, a0, bb.y);
            acc_fma(c1, a1, bb.y, two);
        }
    } else if (full) {
        // Diagonal tile: local j > local i.
        const unsigned long long* B =
            reinterpret_cast<const unsigned long long*>(snb);
        const unsigned long long a0 = pack2(p[ib + tid      ], t[ib + tid      ]);
        const unsigned long long a1 = pack2(p[ib + tid + NTH], t[ib + tid + NTH]);
        #pragma unroll 8
        for (int k = tid + 1; k < TILE; ++k) acc_alu(c0, a0, B[k]);
        #pragma unroll 8
        for (int k = tid + NTH + 1; k < TILE; ++k) acc_fma(c1, a1, B[k], two);
    } else {
        // Partial tile (not hit for n=8192; kept for generality).
        const unsigned long long* B =
            reinterpret_cast<const unsigned long long*>(snb);
        #pragma unroll
        for (int r = 0; r < 2; ++r) {
            const int i = ib + tid + r * NTH;
            if (i < n) {
                const unsigned long long a = pack2(p[i], t[i]);
                for (int k = 0; k < jlim; ++k)
                    if (jb + k > i) acc_alu(c0, a, B[k]);
            }
        }
    }

    // Warp reduction: single REDUX.SUM.
    unsigned int cnt = __reduce_add_sync(0xFFFFFFFFu, c0 + c1);

    __shared__ unsigned int wsum[NTH / 32];
    if ((tid & 31) == 0) wsum[tid >> 5] = cnt;
    __syncthreads();

    if (tid == 0) {
        unsigned int total = 0;
        #pragma unroll
        for (int w = 0; w < NTH / 32; ++w) total += wsum[w];

        // One atomic: low 40 bits accumulate D, high bits count finished
        // blocks. The returned old value tells us if we're last -- the count
        // arrived via the same atomic, so no fence is needed.
        const unsigned long long pkt =
            (unsigned long long)total | (1ULL << 40);
        const unsigned long long old = atomicAdd(&g_cnt, pkt);
        if ((old >> 40) == (unsigned long long)(gridDim.x - 1)) {
            const unsigned long long D = (old + pkt) & ((1ULL << 40) - 1ULL);
            const double nn = (double)n;
            out[0] = (float)(4.0 * (double)D / (nn * (nn - 1.0)));
            atomicExch(&g_cnt, 0ULL);   // reset for next graph replay
        }
    }
}

extern "C" void kernel_launch(void* const* d_in, const int* in_sizes, int n_in,
                              void* d_out, int out_size)
{
    const float* predictions = (const float*)d_in[0];
    const float* true_labels = (const float*)d_in[1];
    float* out = (float*)d_out;
    const int n = in_sizes[0];

    const int ntiles = (n + TILE - 1) / TILE;
    const int nblocks = ntiles * (ntiles + 1) / 2;

    kt_kernel<<<nblocks, NTH>>>(predictions, true_labels, out, n);
}